// round 7
// baseline (speedup 1.0000x reference)
#include <cuda_runtime.h>
#include <math.h>

typedef unsigned long long u64;

// Problem constants
#define Bn 4
#define Tn 2048
#define Cn 1024
#define Mtot (Bn * Tn)      // 8192
#define HALF_C (Cn / 2)     // 512
#define NTILE (Tn / 128)    // 16
#define NTRI (NTILE * (NTILE + 1) / 2)   // 136

// Scratch in device globals (no allocation allowed)
__device__ float g_Q[(size_t)Mtot * Cn];
__device__ float g_K[(size_t)Mtot * Cn];
__device__ float g_V[(size_t)Mtot * Cn];
__device__ float g_O[(size_t)Mtot * Cn];
__device__ float g_S[(size_t)Bn * Tn * Tn];
__device__ float g_cos[(size_t)Tn * HALF_C];
__device__ float g_sin[(size_t)Tn * HALF_C];

// ---------------------------------------------------------------------------
// RoPE table: cos/sin of fp32 angle (t * inv_freq), evaluated in fp64 so we
// don't depend on fast-math sinf argument reduction at |angle| up to 2047 rad.
// ---------------------------------------------------------------------------
__global__ void rope_tab_kernel() {
    int t = blockIdx.x;       // 0..T-1
    int i = threadIdx.x;      // 0..HALF_C-1
    float ex = (float)(2 * i) / (float)Cn;
    float invf = 1.0f / powf(10000.0f, ex);
    float ang = (float)t * invf;
    double sd, cd;
    sincos((double)ang, &sd, &cd);
    g_cos[(size_t)t * HALF_C + i] = (float)cd;
    g_sin[(size_t)t * HALF_C + i] = (float)sd;
}

// unpack halves of a packed f32x2 accumulator
__device__ __forceinline__ float lo32(u64 v) { return __uint_as_float((unsigned)v); }
__device__ __forceinline__ float hi32(u64 v) { return __uint_as_float((unsigned)(v >> 32)); }

// 8x8 micro-tile as four 4x4 quads over a BK=16 stage, packed fp32x2 FMA.
// Thread (tx,ty) owns cols {tx*4..+3} u {64+tx*4..+3}, rows {ty*4..+3} u
// {64+ty*4..+3}. B reads are 2x LDS.128 at 16B*lane stride: conflict-free.
// accp[i][0..1] = cols tx*4+{0,1},{2,3}; accp[i][2..3] = 64+tx*4+{0,1},{2,3}.
// Rows: i<4 -> ty*4+i ; i>=4 -> 64+ty*4+(i-4). Each fma.rn.f32x2 lane is an
// exact fp32 FMA (rn) — numerics identical to scalar FFMA.
#define MICRO_BODY16_X2(AS, BS)                                              \
    _Pragma("unroll")                                                        \
    for (int kk = 0; kk < 16; kk++) {                                        \
        float4 a0 = *(const float4*)&AS[kk][ty * 4];                         \
        float4 a1 = *(const float4*)&AS[kk][64 + ty * 4];                    \
        float4 bq0 = *(const float4*)&BS[kk][tx * 4];                        \
        float4 bq1 = *(const float4*)&BS[kk][64 + tx * 4];                   \
        u64 b2_0, b2_1, b2_2, b2_3;                                          \
        asm("mov.b64 %0, {%1, %2};" : "=l"(b2_0)                             \
            : "r"(__float_as_uint(bq0.x)), "r"(__float_as_uint(bq0.y)));     \
        asm("mov.b64 %0, {%1, %2};" : "=l"(b2_1)                             \
            : "r"(__float_as_uint(bq0.z)), "r"(__float_as_uint(bq0.w)));     \
        asm("mov.b64 %0, {%1, %2};" : "=l"(b2_2)                             \
            : "r"(__float_as_uint(bq1.x)), "r"(__float_as_uint(bq1.y)));     \
        asm("mov.b64 %0, {%1, %2};" : "=l"(b2_3)                             \
            : "r"(__float_as_uint(bq1.z)), "r"(__float_as_uint(bq1.w)));     \
        float av[8] = {a0.x, a0.y, a0.z, a0.w, a1.x, a1.y, a1.z, a1.w};      \
        _Pragma("unroll")                                                    \
        for (int i = 0; i < 8; i++) {                                        \
            u64 a2;                                                          \
            unsigned au = __float_as_uint(av[i]);                            \
            asm("mov.b64 %0, {%1, %1};" : "=l"(a2) : "r"(au));               \
            asm("fma.rn.f32x2 %0, %1, %2, %0;" : "+l"(accp[i][0]) : "l"(a2), "l"(b2_0)); \
            asm("fma.rn.f32x2 %0, %1, %2, %0;" : "+l"(accp[i][1]) : "l"(a2), "l"(b2_1)); \
            asm("fma.rn.f32x2 %0, %1, %2, %0;" : "+l"(accp[i][2]) : "l"(a2), "l"(b2_2)); \
            asm("fma.rn.f32x2 %0, %1, %2, %0;" : "+l"(accp[i][3]) : "l"(a2), "l"(b2_3)); \
        }                                                                    \
    }

// Transposed store of one 8-float A row segment into As[k][row]
#define STORE_A(BUFA, SEG, ROW, V0, V1)                                      \
    BUFA[(SEG) + 0][ROW] = V0.x; BUFA[(SEG) + 1][ROW] = V0.y;                \
    BUFA[(SEG) + 2][ROW] = V0.z; BUFA[(SEG) + 3][ROW] = V0.w;                \
    BUFA[(SEG) + 4][ROW] = V1.x; BUFA[(SEG) + 5][ROW] = V1.y;                \
    BUFA[(SEG) + 6][ROW] = V1.z; BUFA[(SEG) + 7][ROW] = V1.w;

#define DECL_ACCP()                                                          \
    u64 accp[8][4];                                                          \
    _Pragma("unroll")                                                        \
    for (int i = 0; i < 8; i++)                                              \
        _Pragma("unroll")                                                    \
        for (int j = 0; j < 4; j++) accp[i][j] = 0ULL;

// row index of micro-row i within the 128-row tile
#define ROWMAP(i) ((i) < 4 ? (ty * 4 + (i)) : (64 + ty * 4 + (i) - 4))

// ---------------------------------------------------------------------------
// Fused QKV projection: for z = 0,1,2 computes X @ {Wq,Wk,Wv} + bias with
// RoPE fused for z<=1. 128x128 tile, BK=16, double-buffered smem, 256 thr.
// ---------------------------------------------------------------------------
__global__ __launch_bounds__(256) void qkv_proj(
    const float* __restrict__ X,
    const float* __restrict__ Wq, const float* __restrict__ bq,
    const float* __restrict__ Wk, const float* __restrict__ bk_,
    const float* __restrict__ Wv, const float* __restrict__ bv_)
{
    const int mode = blockIdx.z;
    const float* W    = (mode == 0) ? Wq : (mode == 1) ? Wk : Wv;
    const float* bias = (mode == 0) ? bq : (mode == 1) ? bk_ : bv_;
    float* Out        = (mode == 0) ? g_Q : (mode == 1) ? g_K : g_V;
    const int rope = (mode <= 1);

    const int n0 = blockIdx.x * 128;
    const int m0 = blockIdx.y * 128;
    const int tid = threadIdx.x;
    const int tx = tid & 15;        // N
    const int ty = tid >> 4;        // M

    __shared__ __align__(16) float As[2][16][128];
    __shared__ __align__(16) float Bs[2][16][128];

    DECL_ACCP();

    const int arow = tid >> 1;            // 0..127
    const int aseg = (tid & 1) * 8;       // 0 or 8
    const int brow = tid >> 4;            // 0..15 (k within stage)
    const int bcol = (tid & 15) * 8;      // 0..120

    const float* Ap = &X[(size_t)(m0 + arow) * Cn + aseg];
    const float* Wp = &W[(size_t)brow * Cn + n0 + bcol];

    // stage 0
    {
        float4 a0 = *(const float4*)&Ap[0];
        float4 a1 = *(const float4*)&Ap[4];
        float4 b0 = *(const float4*)&Wp[0];
        float4 b1 = *(const float4*)&Wp[4];
        STORE_A(As[0], aseg, arow, a0, a1);
        *(float4*)&Bs[0][brow][bcol] = b0;
        *(float4*)&Bs[0][brow][bcol + 4] = b1;
    }
    __syncthreads();

    int buf = 0;
    for (int k0 = 16; k0 < Cn; k0 += 16) {
        float4 a0 = *(const float4*)&Ap[k0];
        float4 a1 = *(const float4*)&Ap[k0 + 4];
        float4 b0 = *(const float4*)&Wp[(size_t)k0 * Cn];
        float4 b1 = *(const float4*)&Wp[(size_t)k0 * Cn + 4];
        MICRO_BODY16_X2(As[buf], Bs[buf]);
        STORE_A(As[buf ^ 1], aseg, arow, a0, a1);
        *(float4*)&Bs[buf ^ 1][brow][bcol] = b0;
        *(float4*)&Bs[buf ^ 1][brow][bcol + 4] = b1;
        __syncthreads();
        buf ^= 1;
    }
    MICRO_BODY16_X2(As[buf], Bs[buf]);

    const int ncA = n0 + tx * 4;          // first 4-col group
    const int ncB = n0 + 64 + tx * 4;     // second 4-col group
    float bvA[4], bvB[4];
#pragma unroll
    for (int j = 0; j < 4; j++) { bvA[j] = bias[ncA + j]; bvB[j] = bias[ncB + j]; }

#pragma unroll
    for (int i = 0; i < 8; i++) {
        int m = m0 + ROWMAP(i);
        float vA[4], vB[4];
        vA[0] = lo32(accp[i][0]) + bvA[0]; vA[1] = hi32(accp[i][0]) + bvA[1];
        vA[2] = lo32(accp[i][1]) + bvA[2]; vA[3] = hi32(accp[i][1]) + bvA[3];
        vB[0] = lo32(accp[i][2]) + bvB[0]; vB[1] = hi32(accp[i][2]) + bvB[1];
        vB[2] = lo32(accp[i][3]) + bvB[2]; vB[3] = hi32(accp[i][3]) + bvB[3];
        if (rope) {
            int t = m & (Tn - 1);
            const size_t baseA = (size_t)t * HALF_C + (ncA >> 1);
            const size_t baseB = (size_t)t * HALF_C + (ncB >> 1);
#pragma unroll
            for (int j = 0; j < 4; j += 2) {
                float c = g_cos[baseA + (j >> 1)];
                float s = g_sin[baseA + (j >> 1)];
                float x0 = vA[j], x1 = vA[j + 1];
                vA[j] = x0 * c - x1 * s;  vA[j + 1] = x1 * c + x0 * s;
                c = g_cos[baseB + (j >> 1)];
                s = g_sin[baseB + (j >> 1)];
                x0 = vB[j]; x1 = vB[j + 1];
                vB[j] = x0 * c - x1 * s;  vB[j + 1] = x1 * c + x0 * s;
            }
        }
        *(float4*)&Out[(size_t)m * Cn + ncA] = make_float4(vA[0], vA[1], vA[2], vA[3]);
        *(float4*)&Out[(size_t)m * Cn + ncB] = make_float4(vB[0], vB[1], vB[2], vB[3]);
    }
}

// ---------------------------------------------------------------------------
// Final projection: out = g_O @ Wo + bo.
// ---------------------------------------------------------------------------
__global__ __launch_bounds__(256) void out_proj(
    const float* __restrict__ W, const float* __restrict__ bias,
    float* __restrict__ Out)
{
    const int n0 = blockIdx.x * 128;
    const int m0 = blockIdx.y * 128;
    const int tid = threadIdx.x;
    const int tx = tid & 15;
    const int ty = tid >> 4;

    __shared__ __align__(16) float As[2][16][128];
    __shared__ __align__(16) float Bs[2][16][128];

    DECL_ACCP();

    const int arow = tid >> 1;
    const int aseg = (tid & 1) * 8;
    const int brow = tid >> 4;
    const int bcol = (tid & 15) * 8;

    const float* Ap = &g_O[(size_t)(m0 + arow) * Cn + aseg];
    const float* Wp = &W[(size_t)brow * Cn + n0 + bcol];

    {
        float4 a0 = *(const float4*)&Ap[0];
        float4 a1 = *(const float4*)&Ap[4];
        float4 b0 = *(const float4*)&Wp[0];
        float4 b1 = *(const float4*)&Wp[4];
        STORE_A(As[0], aseg, arow, a0, a1);
        *(float4*)&Bs[0][brow][bcol] = b0;
        *(float4*)&Bs[0][brow][bcol + 4] = b1;
    }
    __syncthreads();

    int buf = 0;
    for (int k0 = 16; k0 < Cn; k0 += 16) {
        float4 a0 = *(const float4*)&Ap[k0];
        float4 a1 = *(const float4*)&Ap[k0 + 4];
        float4 b0 = *(const float4*)&Wp[(size_t)k0 * Cn];
        float4 b1 = *(const float4*)&Wp[(size_t)k0 * Cn + 4];
        MICRO_BODY16_X2(As[buf], Bs[buf]);
        STORE_A(As[buf ^ 1], aseg, arow, a0, a1);
        *(float4*)&Bs[buf ^ 1][brow][bcol] = b0;
        *(float4*)&Bs[buf ^ 1][brow][bcol + 4] = b1;
        __syncthreads();
        buf ^= 1;
    }
    MICRO_BODY16_X2(As[buf], Bs[buf]);

    const int ncA = n0 + tx * 4;
    const int ncB = n0 + 64 + tx * 4;
    float bvA[4], bvB[4];
#pragma unroll
    for (int j = 0; j < 4; j++) { bvA[j] = bias[ncA + j]; bvB[j] = bias[ncB + j]; }

#pragma unroll
    for (int i = 0; i < 8; i++) {
        int m = m0 + ROWMAP(i);
        *(float4*)&Out[(size_t)m * Cn + ncA] = make_float4(
            lo32(accp[i][0]) + bvA[0], hi32(accp[i][0]) + bvA[1],
            lo32(accp[i][1]) + bvA[2], hi32(accp[i][1]) + bvA[3]);
        *(float4*)&Out[(size_t)m * Cn + ncB] = make_float4(
            lo32(accp[i][2]) + bvB[0], hi32(accp[i][2]) + bvB[1],
            lo32(accp[i][3]) + bvB[2], hi32(accp[i][3]) + bvB[3]);
    }
}

// ---------------------------------------------------------------------------
// QK^T (NT gemm): S[b,t,s] = scale * sum_c Q[b,t,c]*K[b,s,c].
// Triangular-compacted grid: blockIdx.x in [0, NTRI) -> (ti, si), si <= ti.
// ---------------------------------------------------------------------------
__global__ __launch_bounds__(256) void qkt_gemm(float scale)
{
    // invert l = ti*(ti+1)/2 + si
    const int l = blockIdx.x;
    int ti = (int)((sqrtf(8.0f * (float)l + 1.0f) - 1.0f) * 0.5f);
    while ((ti + 1) * (ti + 2) / 2 <= l) ti++;   // fix float rounding
    while (ti * (ti + 1) / 2 > l) ti--;
    const int si = l - ti * (ti + 1) / 2;

    const int b  = blockIdx.z;
    const int s0 = si * 128;
    const int t0 = ti * 128;
    const float* Q  = g_Q + (size_t)b * Tn * Cn;
    const float* Kp = g_K + (size_t)b * Tn * Cn;
    float* S = g_S + (size_t)b * Tn * Tn;

    const int tid = threadIdx.x;
    const int tx = tid & 15;    // s
    const int ty = tid >> 4;    // t

    __shared__ __align__(16) float As[2][16][128];
    __shared__ __align__(16) float Bs[2][16][128];

    DECL_ACCP();

    const int arow = tid >> 1;
    const int aseg = (tid & 1) * 8;

    const float* Qp = &Q [(size_t)(t0 + arow) * Cn + aseg];
    const float* Kq = &Kp[(size_t)(s0 + arow) * Cn + aseg];

    {
        float4 a0 = *(const float4*)&Qp[0];
        float4 a1 = *(const float4*)&Qp[4];
        float4 b0 = *(const float4*)&Kq[0];
        float4 b1 = *(const float4*)&Kq[4];
        STORE_A(As[0], aseg, arow, a0, a1);
        STORE_A(Bs[0], aseg, arow, b0, b1);
    }
    __syncthreads();

    int buf = 0;
    for (int k0 = 16; k0 < Cn; k0 += 16) {
        float4 a0 = *(const float4*)&Qp[k0];
        float4 a1 = *(const float4*)&Qp[k0 + 4];
        float4 b0 = *(const float4*)&Kq[k0];
        float4 b1 = *(const float4*)&Kq[k0 + 4];
        MICRO_BODY16_X2(As[buf], Bs[buf]);
        STORE_A(As[buf ^ 1], aseg, arow, a0, a1);
        STORE_A(Bs[buf ^ 1], aseg, arow, b0, b1);
        __syncthreads();
        buf ^= 1;
    }
    MICRO_BODY16_X2(As[buf], Bs[buf]);

    const int scA = s0 + tx * 4;
    const int scB = s0 + 64 + tx * 4;
#pragma unroll
    for (int i = 0; i < 8; i++) {
        int t = t0 + ROWMAP(i);
        *(float4*)&S[(size_t)t * Tn + scA] = make_float4(
            lo32(accp[i][0]) * scale, hi32(accp[i][0]) * scale,
            lo32(accp[i][1]) * scale, hi32(accp[i][1]) * scale);
        *(float4*)&S[(size_t)t * Tn + scB] = make_float4(
            lo32(accp[i][2]) * scale, hi32(accp[i][2]) * scale,
            lo32(accp[i][3]) * scale, hi32(accp[i][3]) * scale);
    }
}

// ---------------------------------------------------------------------------
// Causal softmax in-place on g_S. One block per row; zeros above diagonal.
// Warp-shuffle reductions; single smem stage across the 8 warps.
// ---------------------------------------------------------------------------
__global__ __launch_bounds__(256) void softmax_causal()
{
    const int row = blockIdx.x;           // 0..8191
    const int b = row >> 11;
    const int t = row & (Tn - 1);
    float* S = g_S + ((size_t)b * Tn + t) * Tn;
    const int tid = threadIdx.x;
    const int lane = tid & 31;
    const int warp = tid >> 5;

    __shared__ float red[8];

    float e[8];
    float mx = -3.4e38f;
#pragma unroll
    for (int i = 0; i < 8; i++) {
        int s = tid + i * 256;
        float v = (s <= t) ? S[s] : -3.4e38f;
        e[i] = v;
        mx = fmaxf(mx, v);
    }
#pragma unroll
    for (int off = 16; off > 0; off >>= 1)
        mx = fmaxf(mx, __shfl_xor_sync(0xffffffffu, mx, off));
    if (lane == 0) red[warp] = mx;
    __syncthreads();
    {
        float m = red[lane & 7];
#pragma unroll
        for (int off = 4; off > 0; off >>= 1)
            m = fmaxf(m, __shfl_xor_sync(0xffffffffu, m, off));
        mx = m;   // uniform across warp
    }

    float sum = 0.f;
#pragma unroll
    for (int i = 0; i < 8; i++) {
        int s = tid + i * 256;
        float ev = (s <= t) ? expf(e[i] - mx) : 0.f;
        e[i] = ev;
        sum += ev;
    }
#pragma unroll
    for (int off = 16; off > 0; off >>= 1)
        sum += __shfl_xor_sync(0xffffffffu, sum, off);
    __syncthreads();          // red[] reuse safe
    if (lane == 0) red[warp] = sum;
    __syncthreads();
    {
        float s2 = red[lane & 7];
#pragma unroll
        for (int off = 4; off > 0; off >>= 1)
            s2 += __shfl_xor_sync(0xffffffffu, s2, off);
        sum = s2;
    }

    float inv = 1.0f / sum;
#pragma unroll
    for (int i = 0; i < 8; i++) {
        S[tid + i * 256] = e[i] * inv;
    }
}

// ---------------------------------------------------------------------------
// PV (NN gemm): O[b,t,c] = sum_s P[b,t,s] * V[b,s,c].
// k-loop limited to s < t0+128 (P zero above diagonal).
// ---------------------------------------------------------------------------
__global__ __launch_bounds__(256) void pv_gemm()
{
    const int b  = blockIdx.z;
    const int n0 = blockIdx.x * 128;   // c
    const int t0 = blockIdx.y * 128;   // t
    const float* P = g_S + (size_t)b * Tn * Tn;
    const float* V = g_V + (size_t)b * Tn * Cn;
    float* O = g_O + (size_t)b * Tn * Cn;

    const int tid = threadIdx.x;
    const int tx = tid & 15;
    const int ty = tid >> 4;

    __shared__ __align__(16) float As[2][16][128];
    __shared__ __align__(16) float Bs[2][16][128];

    DECL_ACCP();

    const int arow = tid >> 1;
    const int aseg = (tid & 1) * 8;
    const int brow = tid >> 4;
    const int bcol = (tid & 15) * 8;

    const int kmax = t0 + 128;   // multiple of 16

    const float* Pp = &P[(size_t)(t0 + arow) * Tn + aseg];
    const float* Vp = &V[(size_t)brow * Cn + n0 + bcol];

    {
        float4 a0 = *(const float4*)&Pp[0];
        float4 a1 = *(const float4*)&Pp[4];
        float4 b0 = *(const float4*)&Vp[0];
        float4 b1 = *(const float4*)&Vp[4];
        STORE_A(As[0], aseg, arow, a0, a1);
        *(float4*)&Bs[0][brow][bcol] = b0;
        *(float4*)&Bs[0][brow][bcol + 4] = b1;
    }
    __syncthreads();

    int buf = 0;
    for (int k0 = 16; k0 < kmax; k0 += 16) {
        float4 a0 = *(const float4*)&Pp[k0];
        float4 a1 = *(const float4*)&Pp[k0 + 4];
        float4 b0 = *(const float4*)&Vp[(size_t)k0 * Cn];
        float4 b1 = *(const float4*)&Vp[(size_t)k0 * Cn + 4];
        MICRO_BODY16_X2(As[buf], Bs[buf]);
        STORE_A(As[buf ^ 1], aseg, arow, a0, a1);
        *(float4*)&Bs[buf ^ 1][brow][bcol] = b0;
        *(float4*)&Bs[buf ^ 1][brow][bcol + 4] = b1;
        __syncthreads();
        buf ^= 1;
    }
    MICRO_BODY16_X2(As[buf], Bs[buf]);

    const int ncA = n0 + tx * 4;
    const int ncB = n0 + 64 + tx * 4;
#pragma unroll
    for (int i = 0; i < 8; i++) {
        int t = t0 + ROWMAP(i);
        *(float4*)&O[(size_t)t * Cn + ncA] = make_float4(
            lo32(accp[i][0]), hi32(accp[i][0]),
            lo32(accp[i][1]), hi32(accp[i][1]));
        *(float4*)&O[(size_t)t * Cn + ncB] = make_float4(
            lo32(accp[i][2]), hi32(accp[i][2]),
            lo32(accp[i][3]), hi32(accp[i][3]));
    }
}

// ---------------------------------------------------------------------------
// Launch
// ---------------------------------------------------------------------------
extern "C" void kernel_launch(void* const* d_in, const int* in_sizes, int n_in,
                              void* d_out, int out_size)
{
    const float* x  = (const float*)d_in[0];
    const float* Wq = (const float*)d_in[1];
    const float* bq = (const float*)d_in[2];
    const float* Wk = (const float*)d_in[3];
    const float* bk = (const float*)d_in[4];
    const float* Wv = (const float*)d_in[5];
    const float* bv = (const float*)d_in[6];
    const float* Wo = (const float*)d_in[7];
    const float* bo = (const float*)d_in[8];
    float* out = (float*)d_out;

    // RoPE cos/sin tables (deterministic, recomputed each call)
    rope_tab_kernel<<<Tn, HALF_C>>>();

    dim3 gQKV(Cn / 128, Mtot / 128, 3);   // (8, 64, 3)
    qkv_proj<<<gQKV, 256>>>(x, Wq, bq, Wk, bk, Wv, bv);

    dim3 gQKT(NTRI, 1, Bn);               // (136, 1, 4) — lower-tri tiles only
    qkt_gemm<<<gQKT, 256>>>(1.0f / 32.0f);   // 1/sqrt(1024)

    softmax_causal<<<Mtot, 256>>>();

    dim3 gPV(Cn / 128, Tn / 128, Bn);     // (8,16,4)
    pv_gemm<<<gPV, 256>>>();

    dim3 gProj(Cn / 128, Mtot / 128);     // (8, 64)
    out_proj<<<gProj, 256>>>(Wo, bo, out);
}

// round 13
// speedup vs baseline: 1.6780x; 1.6780x over previous
#include <cuda_runtime.h>
#include <cuda_bf16.h>
#include <math.h>
#include <stdint.h>

typedef __nv_bfloat16 bf16;
typedef unsigned long long u64;

// Problem constants
#define Bn 4
#define Tn 2048
#define Cn 1024
#define Mtot (Bn * Tn)      // 8192
#define NTILE (Tn / 128)    // 16
#define NTRI (NTILE * (NTILE + 1) / 2)   // 136

// Scratch in device globals (no allocation allowed). 256B-aligned for 16B ops.
__device__ __align__(256) bf16 g_Xhi[(size_t)Mtot * Cn];
__device__ __align__(256) bf16 g_Xlo[(size_t)Mtot * Cn];
__device__ __align__(256) bf16 g_Wthi[(size_t)4 * Cn * Cn];   // [z][n][k] = W_z[k][n]
__device__ __align__(256) bf16 g_Wtlo[(size_t)4 * Cn * Cn];
__device__ __align__(256) bf16 g_Qhi[(size_t)Mtot * Cn];
__device__ __align__(256) bf16 g_Qlo[(size_t)Mtot * Cn];
__device__ __align__(256) bf16 g_Khi[(size_t)Mtot * Cn];
__device__ __align__(256) bf16 g_Klo[(size_t)Mtot * Cn];
__device__ __align__(256) bf16 g_Vthi[(size_t)Bn * Cn * Tn];  // [b][c][s]
__device__ __align__(256) bf16 g_Vtlo[(size_t)Bn * Cn * Tn];
__device__ __align__(256) float g_S[(size_t)Bn * Tn * Tn];
__device__ __align__(256) bf16 g_Phi[(size_t)Bn * Tn * Tn];
__device__ __align__(256) bf16 g_Plo[(size_t)Bn * Tn * Tn];
__device__ __align__(256) bf16 g_Ohi[(size_t)Mtot * Cn];
__device__ __align__(256) bf16 g_Olo[(size_t)Mtot * Cn];
__device__ __align__(256) float2 g_cs[(size_t)Tn * (Cn / 2)]; // (cos, sin)

// ---------------------------------------------------------------------------
// PTX helpers (all compute_80-level — no 'a'-suffix features)
// ---------------------------------------------------------------------------
__device__ __forceinline__ uint32_t smem_u32(const void* p) {
    uint32_t a;
    asm("{ .reg .u64 t; cvta.to.shared.u64 t, %1; cvt.u32.u64 %0, t; }" : "=r"(a) : "l"(p));
    return a;
}
#define CP_ASYNC16(dst, src) \
    asm volatile("cp.async.cg.shared.global [%0], [%1], 16;" :: "r"(dst), "l"(src))
#define CP_COMMIT() asm volatile("cp.async.commit_group;" ::: "memory")
#define CP_WAIT1()  asm volatile("cp.async.wait_group 1;" ::: "memory")
#define CP_WAIT0()  asm volatile("cp.async.wait_group 0;" ::: "memory")

__device__ __forceinline__ void ldmx4(uint32_t r[4], uint32_t addr) {
    asm volatile("ldmatrix.sync.aligned.m8n8.x4.shared.b16 {%0,%1,%2,%3}, [%4];"
        : "=r"(r[0]), "=r"(r[1]), "=r"(r[2]), "=r"(r[3]) : "r"(addr));
}
__device__ __forceinline__ void mma16816(float d[4], const uint32_t a[4], uint32_t b0, uint32_t b1) {
    asm volatile("mma.sync.aligned.m16n8k16.row.col.f32.bf16.bf16.f32 "
        "{%0,%1,%2,%3}, {%4,%5,%6,%7}, {%8,%9}, {%0,%1,%2,%3};"
        : "+f"(d[0]), "+f"(d[1]), "+f"(d[2]), "+f"(d[3])
        : "r"(a[0]), "r"(a[1]), "r"(a[2]), "r"(a[3]), "r"(b0), "r"(b1));
}

__device__ __forceinline__ void bsplit(float x, bf16& h, bf16& l) {
    h = __float2bfloat16_rn(x);
    l = __float2bfloat16_rn(x - __bfloat162float(h));
}
__device__ __forceinline__ uint32_t pack2(bf16 a, bf16 b) {
    union { bf16 v[2]; uint32_t u; } t;
    t.v[0] = a; t.v[1] = b;
    return t.u;
}

// ---------------------------------------------------------------------------
// Prep kernels
// ---------------------------------------------------------------------------
__global__ void rope_tab_kernel() {
    int t = blockIdx.x;
    int i = threadIdx.x;      // 0..511
    float ex = (float)(2 * i) / (float)Cn;
    float invf = 1.0f / powf(10000.0f, ex);
    float ang = (float)t * invf;
    double sd, cd;
    sincos((double)ang, &sd, &cd);
    g_cs[(size_t)t * (Cn / 2) + i] = make_float2((float)cd, (float)sd);
}

__global__ void split_x_kernel(const float* __restrict__ X) {
    size_t i = (size_t)blockIdx.x * 256 + threadIdx.x;   // float4 index
    float4 v = ((const float4*)X)[i];
    union { bf16 b[4]; u64 q; } H, L;
    bsplit(v.x, H.b[0], L.b[0]);
    bsplit(v.y, H.b[1], L.b[1]);
    bsplit(v.z, H.b[2], L.b[2]);
    bsplit(v.w, H.b[3], L.b[3]);
    ((u64*)g_Xhi)[i] = H.q;
    ((u64*)g_Xlo)[i] = L.q;
}

__global__ void transpose_split_w(const float* __restrict__ Wq, const float* __restrict__ Wk,
                                  const float* __restrict__ Wv, const float* __restrict__ Wo)
{
    const int z = blockIdx.z;
    const float* W = (z == 0) ? Wq : (z == 1) ? Wk : (z == 2) ? Wv : Wo;
    bf16* Oh = g_Wthi + (size_t)z * Cn * Cn;
    bf16* Ol = g_Wtlo + (size_t)z * Cn * Cn;
    __shared__ float tile[32][33];
    int tx = threadIdx.x, ty = threadIdx.y;
    int kb = blockIdx.y * 32, nb = blockIdx.x * 32;
#pragma unroll
    for (int j = 0; j < 4; j++)
        tile[ty + j * 8][tx] = W[(size_t)(kb + ty + j * 8) * Cn + nb + tx];
    __syncthreads();
#pragma unroll
    for (int j = 0; j < 4; j++) {
        int n = nb + ty + j * 8, k = kb + tx;
        bf16 h, l;
        bsplit(tile[tx][ty + j * 8], h, l);
        Oh[(size_t)n * Cn + k] = h;
        Ol[(size_t)n * Cn + k] = l;
    }
}

// ---------------------------------------------------------------------------
// Warp-MMA GEMM core. 256 threads = 8 warps (2 M x 4 N), warp tile 64x32.
// smem: double buffer x 4 tiles {Ahi,Alo,Bhi,Blo}, 128 rows x 32 bf16, row
// stride 80B (16B pad -> conflict-free ldmatrix). K-chunk = 32.
// Split-bf16: D += Ahi*Bhi + Ahi*Blo + Alo*Bhi.
// ---------------------------------------------------------------------------
#define KCH 32
#define ROWB 80
#define TILEB (128 * ROWB)       // 10240
#define BUFB (4 * TILEB)         // 40960
#define SMEM_MMA (2 * BUFB)      // 81920

__device__ __forceinline__ void load_chunk(
    uint32_t sb, int buf,
    const bf16* __restrict__ Ah, const bf16* __restrict__ Al, int lda,
    const bf16* __restrict__ Bh, const bf16* __restrict__ Bl, int ldb,
    int koff, int tid)
{
    uint32_t b0 = sb + buf * BUFB;
#pragma unroll
    for (int u = 0; u < 8; u++) {
        int s = tid + u * 256;
        int tile = s >> 9;          // 0..3
        int row = (s >> 2) & 127;
        int sg = s & 3;
        const bf16* gp = (tile == 0) ? Ah : (tile == 1) ? Al : (tile == 2) ? Bh : Bl;
        int ld = (tile < 2) ? lda : ldb;
        const bf16* src = gp + (size_t)row * ld + koff + sg * 8;
        uint32_t dst = b0 + tile * TILEB + (uint32_t)(row * ROWB + sg * 16);
        CP_ASYNC16(dst, src);
    }
}

// Full K mainloop; accumulates into acc[4][4][4].
__device__ __forceinline__ void gemm_ws(float acc[4][4][4],
    const bf16* __restrict__ Ah, const bf16* __restrict__ Al, int lda,
    const bf16* __restrict__ Bh, const bf16* __restrict__ Bl, int ldb,
    int nc, uint32_t sb, int tid)
{
    const int lane = tid & 31, warp = tid >> 5;
    const int wm = (warp >> 2) * 64, wn = (warp & 3) * 32;
    const int lr = lane & 15;
    const uint32_t lcol = (uint32_t)((lane >> 4) * 16);

    load_chunk(sb, 0, Ah, Al, lda, Bh, Bl, ldb, 0, tid);
    CP_COMMIT();
    load_chunk(sb, 1, Ah, Al, lda, Bh, Bl, ldb, KCH, tid);
    CP_COMMIT();

    for (int i = 0; i < nc; i++) {
        int buf = i & 1;
        if (i < nc - 1) { CP_WAIT1(); } else { CP_WAIT0(); }
        __syncthreads();

        uint32_t tb = sb + buf * BUFB;
#pragma unroll
        for (int s = 0; s < 2; s++) {
            uint32_t koffb = (uint32_t)(s * 32) + lcol;   // bytes within row
            uint32_t aH[4][4], aL[4][4];
#pragma unroll
            for (int mi = 0; mi < 4; mi++) {
                uint32_t r = (uint32_t)((wm + mi * 16 + lr) * ROWB) + koffb;
                ldmx4(aH[mi], tb + 0 * TILEB + r);
                ldmx4(aL[mi], tb + 1 * TILEB + r);
            }
            uint32_t bH[2][4], bL[2][4];
#pragma unroll
            for (int h = 0; h < 2; h++) {
                uint32_t r = (uint32_t)((wn + h * 16 + lr) * ROWB) + koffb;
                ldmx4(bH[h], tb + 2 * TILEB + r);
                ldmx4(bL[h], tb + 3 * TILEB + r);
            }
#pragma unroll
            for (int mi = 0; mi < 4; mi++)
#pragma unroll
                for (int ni = 0; ni < 4; ni++) {
                    int h = ni >> 1, w8 = ni & 1;
                    uint32_t bh0 = bH[h][w8], bh1 = bH[h][w8 + 2];
                    uint32_t bl0 = bL[h][w8], bl1 = bL[h][w8 + 2];
                    mma16816(acc[mi][ni], aH[mi], bh0, bh1);
                    mma16816(acc[mi][ni], aH[mi], bl0, bl1);
                    mma16816(acc[mi][ni], aL[mi], bh0, bh1);
                }
        }
        __syncthreads();
        if (i + 2 < nc) {
            load_chunk(sb, buf, Ah, Al, lda, Bh, Bl, ldb, (i + 2) * KCH, tid);
            CP_COMMIT();
        }
    }
}

#define DECL_ACC()                                                           \
    float acc[4][4][4];                                                      \
    _Pragma("unroll")                                                        \
    for (int mi = 0; mi < 4; mi++)                                           \
        _Pragma("unroll")                                                    \
        for (int ni = 0; ni < 4; ni++)                                       \
            _Pragma("unroll")                                                \
            for (int f = 0; f < 4; f++) acc[mi][ni][f] = 0.f;

// ---------------------------------------------------------------------------
// Projection MMA: z = 0(Q,rope), 1(K,rope), 2(V -> transposed hi/lo).
// ---------------------------------------------------------------------------
__global__ __launch_bounds__(256) void proj_mma(
    const float* __restrict__ bq, const float* __restrict__ bk, const float* __restrict__ bv)
{
    extern __shared__ char smem[];
    uint32_t sb = smem_u32(smem);
    int tid = threadIdx.x;
    const int z = blockIdx.z;
    const int n0 = blockIdx.x * 128, m0 = blockIdx.y * 128;

    const bf16* Ah = g_Xhi + (size_t)m0 * Cn;
    const bf16* Al = g_Xlo + (size_t)m0 * Cn;
    const bf16* Bh = g_Wthi + (size_t)z * Cn * Cn + (size_t)n0 * Cn;
    const bf16* Bl = g_Wtlo + (size_t)z * Cn * Cn + (size_t)n0 * Cn;

    DECL_ACC();
    gemm_ws(acc, Ah, Al, Cn, Bh, Bl, Cn, Cn / KCH, sb, tid);

    const float* bias = (z == 0) ? bq : (z == 1) ? bk : bv;
    const int lane = tid & 31, warp = tid >> 5;
    const int wm = (warp >> 2) * 64, wn = (warp & 3) * 32;
    const int gid = lane >> 2, t4 = lane & 3;

#pragma unroll
    for (int mi = 0; mi < 4; mi++)
#pragma unroll
        for (int ni = 0; ni < 4; ni++) {
            int cc = wn + ni * 8 + t4 * 2;
            int n = n0 + cc;
            float b0v = bias[n], b1v = bias[n + 1];
#pragma unroll
            for (int half = 0; half < 2; half++) {
                float v0 = acc[mi][ni][half * 2 + 0] + b0v;
                float v1 = acc[mi][ni][half * 2 + 1] + b1v;
                int m = m0 + wm + mi * 16 + gid + half * 8;
                int bb = m >> 11, t = m & (Tn - 1);
                if (z < 2) {
                    float2 cs = g_cs[(size_t)t * (Cn / 2) + (n >> 1)];
                    float r0 = v0 * cs.x - v1 * cs.y;
                    float r1 = v1 * cs.x + v0 * cs.y;
                    bf16 h0, l0, h1, l1;
                    bsplit(r0, h0, l0);
                    bsplit(r1, h1, l1);
                    bf16* dh = ((z == 0) ? g_Qhi : g_Khi);
                    bf16* dl = ((z == 0) ? g_Qlo : g_Klo);
                    *(uint32_t*)&dh[(size_t)m * Cn + n] = pack2(h0, h1);
                    *(uint32_t*)&dl[(size_t)m * Cn + n] = pack2(l0, l1);
                } else {
                    bf16 h0, l0, h1, l1;
                    bsplit(v0, h0, l0);
                    bsplit(v1, h1, l1);
                    size_t d0 = ((size_t)bb * Cn + n) * Tn + t;
                    size_t d1 = ((size_t)bb * Cn + n + 1) * Tn + t;
                    g_Vthi[d0] = h0; g_Vtlo[d0] = l0;
                    g_Vthi[d1] = h1; g_Vtlo[d1] = l1;
                }
            }
        }
}

// ---------------------------------------------------------------------------
// QK^T MMA, triangular grid. S = scale * Q K^T.
// ---------------------------------------------------------------------------
__global__ __launch_bounds__(256) void qkt_mma(float scale)
{
    extern __shared__ char smem[];
    uint32_t sb = smem_u32(smem);
    int tid = threadIdx.x;

    const int l = blockIdx.x;
    int ti = (int)((sqrtf(8.0f * (float)l + 1.0f) - 1.0f) * 0.5f);
    while ((ti + 1) * (ti + 2) / 2 <= l) ti++;
    while (ti * (ti + 1) / 2 > l) ti--;
    const int si = l - ti * (ti + 1) / 2;
    const int b = blockIdx.z;
    const int t0 = ti * 128, s0 = si * 128;

    const bf16* Ah = g_Qhi + ((size_t)b * Tn + t0) * Cn;
    const bf16* Al = g_Qlo + ((size_t)b * Tn + t0) * Cn;
    const bf16* Bh = g_Khi + ((size_t)b * Tn + s0) * Cn;
    const bf16* Bl = g_Klo + ((size_t)b * Tn + s0) * Cn;

    DECL_ACC();
    gemm_ws(acc, Ah, Al, Cn, Bh, Bl, Cn, Cn / KCH, sb, tid);

    const int lane = tid & 31, warp = tid >> 5;
    const int wm = (warp >> 2) * 64, wn = (warp & 3) * 32;
    const int gid = lane >> 2, t4 = lane & 3;

#pragma unroll
    for (int mi = 0; mi < 4; mi++)
#pragma unroll
        for (int ni = 0; ni < 4; ni++) {
            int c = s0 + wn + ni * 8 + t4 * 2;
#pragma unroll
            for (int half = 0; half < 2; half++) {
                int t = t0 + wm + mi * 16 + gid + half * 8;
                float2 v = make_float2(acc[mi][ni][half * 2] * scale,
                                       acc[mi][ni][half * 2 + 1] * scale);
                *(float2*)&g_S[((size_t)b * Tn + t) * Tn + c] = v;
            }
        }
}

// ---------------------------------------------------------------------------
// Causal softmax: read S fp32, write P hi/lo bf16 (zeros above diagonal).
// ---------------------------------------------------------------------------
__global__ __launch_bounds__(256) void softmax_causal()
{
    const int rowi = blockIdx.x;
    const int b = rowi >> 11;
    const int t = rowi & (Tn - 1);
    const float* S = g_S + ((size_t)b * Tn + t) * Tn;
    size_t pbase = ((size_t)b * Tn + t) * Tn;
    const int tid = threadIdx.x;
    const int lane = tid & 31;
    const int warp = tid >> 5;

    __shared__ float red[8];

    float e[8];
    float mx = -3.4e38f;
#pragma unroll
    for (int i = 0; i < 8; i++) {
        int s = tid + i * 256;
        float v = (s <= t) ? S[s] : -3.4e38f;
        e[i] = v;
        mx = fmaxf(mx, v);
    }
#pragma unroll
    for (int off = 16; off > 0; off >>= 1)
        mx = fmaxf(mx, __shfl_xor_sync(0xffffffffu, mx, off));
    if (lane == 0) red[warp] = mx;
    __syncthreads();
    {
        float m = red[lane & 7];
#pragma unroll
        for (int off = 4; off > 0; off >>= 1)
            m = fmaxf(m, __shfl_xor_sync(0xffffffffu, m, off));
        mx = m;
    }

    float sum = 0.f;
#pragma unroll
    for (int i = 0; i < 8; i++) {
        int s = tid + i * 256;
        float ev = (s <= t) ? expf(e[i] - mx) : 0.f;
        e[i] = ev;
        sum += ev;
    }
#pragma unroll
    for (int off = 16; off > 0; off >>= 1)
        sum += __shfl_xor_sync(0xffffffffu, sum, off);
    __syncthreads();
    if (lane == 0) red[warp] = sum;
    __syncthreads();
    {
        float s2 = red[lane & 7];
#pragma unroll
        for (int off = 4; off > 0; off >>= 1)
            s2 += __shfl_xor_sync(0xffffffffu, s2, off);
        sum = s2;
    }

    float inv = 1.0f / sum;
#pragma unroll
    for (int i = 0; i < 8; i++) {
        int s = tid + i * 256;
        bf16 h, l;
        bsplit(e[i] * inv, h, l);
        g_Phi[pbase + s] = h;
        g_Plo[pbase + s] = l;
    }
}

// ---------------------------------------------------------------------------
// PV MMA: O[t,c] = sum_s P[t,s] Vt[c,s]; k limited to t0+128.
// ---------------------------------------------------------------------------
__global__ __launch_bounds__(256) void pv_mma()
{
    extern __shared__ char smem[];
    uint32_t sb = smem_u32(smem);
    int tid = threadIdx.x;
    const int n0 = blockIdx.x * 128;   // c
    const int t0 = blockIdx.y * 128;   // t
    const int b = blockIdx.z;
    const int nc = (t0 + 128) / KCH;

    const bf16* Ah = g_Phi + ((size_t)b * Tn + t0) * Tn;
    const bf16* Al = g_Plo + ((size_t)b * Tn + t0) * Tn;
    const bf16* Bh = g_Vthi + ((size_t)b * Cn + n0) * Tn;
    const bf16* Bl = g_Vtlo + ((size_t)b * Cn + n0) * Tn;

    DECL_ACC();
    gemm_ws(acc, Ah, Al, Tn, Bh, Bl, Tn, nc, sb, tid);

    const int lane = tid & 31, warp = tid >> 5;
    const int wm = (warp >> 2) * 64, wn = (warp & 3) * 32;
    const int gid = lane >> 2, t4 = lane & 3;

#pragma unroll
    for (int mi = 0; mi < 4; mi++)
#pragma unroll
        for (int ni = 0; ni < 4; ni++) {
            int c = n0 + wn + ni * 8 + t4 * 2;
#pragma unroll
            for (int half = 0; half < 2; half++) {
                int t = t0 + wm + mi * 16 + gid + half * 8;
                float v0 = acc[mi][ni][half * 2], v1 = acc[mi][ni][half * 2 + 1];
                bf16 h0, l0, h1, l1;
                bsplit(v0, h0, l0);
                bsplit(v1, h1, l1);
                size_t d = ((size_t)b * Tn + t) * Cn + c;
                *(uint32_t*)&g_Ohi[d] = pack2(h0, h1);
                *(uint32_t*)&g_Olo[d] = pack2(l0, l1);
            }
        }
}

// ---------------------------------------------------------------------------
// Output MMA: out = O @ Wo + bo (fp32 output).
// ---------------------------------------------------------------------------
__global__ __launch_bounds__(256) void out_mma(const float* __restrict__ bo, float* __restrict__ Out)
{
    extern __shared__ char smem[];
    uint32_t sb = smem_u32(smem);
    int tid = threadIdx.x;
    const int n0 = blockIdx.x * 128, m0 = blockIdx.y * 128;

    const bf16* Ah = g_Ohi + (size_t)m0 * Cn;
    const bf16* Al = g_Olo + (size_t)m0 * Cn;
    const bf16* Bh = g_Wthi + (size_t)3 * Cn * Cn + (size_t)n0 * Cn;
    const bf16* Bl = g_Wtlo + (size_t)3 * Cn * Cn + (size_t)n0 * Cn;

    DECL_ACC();
    gemm_ws(acc, Ah, Al, Cn, Bh, Bl, Cn, Cn / KCH, sb, tid);

    const int lane = tid & 31, warp = tid >> 5;
    const int wm = (warp >> 2) * 64, wn = (warp & 3) * 32;
    const int gid = lane >> 2, t4 = lane & 3;

#pragma unroll
    for (int mi = 0; mi < 4; mi++)
#pragma unroll
        for (int ni = 0; ni < 4; ni++) {
            int c = n0 + wn + ni * 8 + t4 * 2;
            float b0v = bo[c], b1v = bo[c + 1];
#pragma unroll
            for (int half = 0; half < 2; half++) {
                int m = m0 + wm + mi * 16 + gid + half * 8;
                float2 v = make_float2(acc[mi][ni][half * 2] + b0v,
                                       acc[mi][ni][half * 2 + 1] + b1v);
                *(float2*)&Out[(size_t)m * Cn + c] = v;
            }
        }
}

// ---------------------------------------------------------------------------
// Launch
// ---------------------------------------------------------------------------
extern "C" void kernel_launch(void* const* d_in, const int* in_sizes, int n_in,
                              void* d_out, int out_size)
{
    const float* x  = (const float*)d_in[0];
    const float* Wq = (const float*)d_in[1];
    const float* bq = (const float*)d_in[2];
    const float* Wk = (const float*)d_in[3];
    const float* bk = (const float*)d_in[4];
    const float* Wv = (const float*)d_in[5];
    const float* bv = (const float*)d_in[6];
    const float* Wo = (const float*)d_in[7];
    const float* bo = (const float*)d_in[8];
    float* out = (float*)d_out;

    cudaFuncSetAttribute(proj_mma, cudaFuncAttributeMaxDynamicSharedMemorySize, SMEM_MMA);
    cudaFuncSetAttribute(qkt_mma, cudaFuncAttributeMaxDynamicSharedMemorySize, SMEM_MMA);
    cudaFuncSetAttribute(pv_mma, cudaFuncAttributeMaxDynamicSharedMemorySize, SMEM_MMA);
    cudaFuncSetAttribute(out_mma, cudaFuncAttributeMaxDynamicSharedMemorySize, SMEM_MMA);

    rope_tab_kernel<<<Tn, Cn / 2>>>();
    split_x_kernel<<<(Mtot * Cn / 4) / 256, 256>>>(x);
    transpose_split_w<<<dim3(32, 32, 4), dim3(32, 8)>>>(Wq, Wk, Wv, Wo);

    proj_mma<<<dim3(Cn / 128, Mtot / 128, 3), 256, SMEM_MMA>>>(bq, bk, bv);

    qkt_mma<<<dim3(NTRI, 1, Bn), 256, SMEM_MMA>>>(1.0f / 32.0f);

    softmax_causal<<<Mtot, 256>>>();

    pv_mma<<<dim3(Cn / 128, Tn / 128, Bn), 256, SMEM_MMA>>>();

    out_mma<<<dim3(Cn / 128, Mtot / 128), 256, SMEM_MMA>>>(bo, out);
}